// round 2
// baseline (speedup 1.0000x reference)
#include <cuda_runtime.h>

#define N_NODES   100000
#define E_PER_REL 150000
#define R_REL     4
#define E_TOTAL   (E_PER_REL * R_REL)
#define WC_COLS   320   // [self(64) | rel0(64) | rel1(64) | rel2(64) | rel3(64)]

// Scratch (device globals — no runtime allocation allowed)
__device__ __align__(128) float g_Y1[(size_t)N_NODES * WC_COLS];   // 128 MB
__device__ __align__(128) float g_Y2[(size_t)N_NODES * WC_COLS];   // 128 MB
__device__ __align__(128) float g_Wc1[128 * WC_COLS];
__device__ __align__(128) float g_Wc2[64 * WC_COLS];
__device__ int g_idx_is64;   // 1 if index buffers are int64, 0 if int32

// ---------------------------------------------------------------------------
// Index-dtype sniff: if buffers are int64 with values < 2^31, every odd 32-bit
// word is zero. For random int32 indices in [0,1e5), P(4096 odd words all 0)~0.
// ---------------------------------------------------------------------------
__global__ void sniff_kernel(const unsigned int* __restrict__ idx) {
    __shared__ int nz;
    if (threadIdx.x == 0) nz = 0;
    __syncthreads();
    for (int i = threadIdx.x; i < 4096; i += blockDim.x)
        if (idx[2 * i + 1] != 0u) nz = 1;
    __syncthreads();
    if (threadIdx.x == 0) g_idx_is64 = (nz == 0) ? 1 : 0;
}

// ---------------------------------------------------------------------------
// Build combined weights: Wc[d][0:64] = Wself, Wc[d][64+64r+o] = sign_r*Wrel[r][d][o]
// ---------------------------------------------------------------------------
__global__ void prep_w_kernel(const float* __restrict__ Wrel,
                              const float* __restrict__ Wself,
                              float* __restrict__ Wc, int din) {
    int idx = blockIdx.x * blockDim.x + threadIdx.x;
    int total = din * WC_COLS;
    if (idx >= total) return;
    int d = idx / WC_COLS;
    int c = idx - d * WC_COLS;
    float v;
    if (c < 64) {
        v = Wself[d * 64 + c];
    } else {
        int r = (c - 64) >> 6;
        int o = (c - 64) & 63;
        v = Wrel[((size_t)r * din + d) * 64 + o];
        if (r == 3) v = -v;   // SUBTRACT_REL = 3
    }
    Wc[idx] = v;
}

// ---------------------------------------------------------------------------
// GEMM: C[M,320] = A[M,K] @ B[K,320], in 64-wide column blocks.
// TILE_M=128, TILE_N=64, K_TILE=64. 256 threads, each 8 rows x 4 cols.
// RELU applies relu to A on load (fuses layer-1 activation).
// ---------------------------------------------------------------------------
template <int K, bool RELU>
__global__ void __launch_bounds__(256) gemm_kernel(const float* __restrict__ A, int lda,
                                                   const float* __restrict__ B,
                                                   float* __restrict__ C) {
    __shared__ float As[128][64];   // 32 KB
    __shared__ float Bs[64][64];    // 16 KB
    const int m0   = blockIdx.x * 128;
    const int cb   = blockIdx.y;          // column block (0..4)
    const int tid  = threadIdx.x;
    const int tcol = tid & 15;            // 16 col-groups of 4
    const int trow = tid >> 4;            // 16 row-groups of 8

    float acc[8][4];
#pragma unroll
    for (int i = 0; i < 8; i++)
#pragma unroll
        for (int j = 0; j < 4; j++) acc[i][j] = 0.f;

#pragma unroll
    for (int k0 = 0; k0 < K; k0 += 64) {
        // Load A tile [128 x 64] (coalesced float4 along k)
#pragma unroll
        for (int p = 0; p < 8; p++) {
            int row = p * 16 + trow;
            int gr  = m0 + row;
            float4 v = make_float4(0.f, 0.f, 0.f, 0.f);
            if (gr < N_NODES) {
                v = *(const float4*)&A[(size_t)gr * lda + k0 + tcol * 4];
                if (RELU) {
                    v.x = fmaxf(v.x, 0.f); v.y = fmaxf(v.y, 0.f);
                    v.z = fmaxf(v.z, 0.f); v.w = fmaxf(v.w, 0.f);
                }
            }
            *(float4*)&As[row][tcol * 4] = v;
        }
        // Load B tile [64 x 64]
#pragma unroll
        for (int p = 0; p < 4; p++) {
            int kk = p * 16 + trow;
            *(float4*)&Bs[kk][tcol * 4] =
                *(const float4*)&B[(size_t)(k0 + kk) * WC_COLS + cb * 64 + tcol * 4];
        }
        __syncthreads();

#pragma unroll 16
        for (int k = 0; k < 64; k++) {
            float4 b = *(float4*)&Bs[k][tcol * 4];
#pragma unroll
            for (int i = 0; i < 8; i++) {
                float a = As[trow * 8 + i][k];
                acc[i][0] += a * b.x;
                acc[i][1] += a * b.y;
                acc[i][2] += a * b.z;
                acc[i][3] += a * b.w;
            }
        }
        __syncthreads();
    }

#pragma unroll
    for (int i = 0; i < 8; i++) {
        int gr = m0 + trow * 8 + i;
        if (gr < N_NODES) {
            float4 o = make_float4(acc[i][0], acc[i][1], acc[i][2], acc[i][3]);
            *(float4*)&C[(size_t)gr * WC_COLS + cb * 64 + tcol * 4] = o;
        }
    }
}

// ---------------------------------------------------------------------------
// Scatter: for each edge e of relation r:
//   Y[dst][0:64] += Y[src][64+64r : 128+64r]   (signs pre-folded into Wc)
// 16 threads per edge, one red.global.add.v4.f32 (16B) per thread.
// Handles int32 or int64 index buffers via g_idx_is64.
// ---------------------------------------------------------------------------
__global__ void __launch_bounds__(256) scatter_kernel(const void* __restrict__ src_v,
                                                      const void* __restrict__ dst_v,
                                                      float* __restrict__ Y) {
    int gid  = blockIdx.x * blockDim.x + threadIdx.x;
    int edge = gid >> 4;
    if (edge >= E_TOTAL) return;
    int sub = gid & 15;
    int r   = edge / E_PER_REL;          // src/dst are [4][150000] row-major

    long long s, d;
    if (g_idx_is64) {
        s = ((const long long*)src_v)[edge];
        d = ((const long long*)dst_v)[edge];
    } else {
        s = ((const int*)src_v)[edge];
        d = ((const int*)dst_v)[edge];
    }

    const float4 v = *(const float4*)&Y[(size_t)s * WC_COLS + 64 + r * 64 + sub * 4];
    float* p = &Y[(size_t)d * WC_COLS + sub * 4];
    asm volatile("red.global.add.v4.f32 [%0], {%1,%2,%3,%4};"
                 :: "l"(p), "f"(v.x), "f"(v.y), "f"(v.z), "f"(v.w)
                 : "memory");
}

// ---------------------------------------------------------------------------
// out = sigmoid(relu(Y2[:, 0:64]))
// ---------------------------------------------------------------------------
__global__ void __launch_bounds__(256) sigmoid_kernel(const float* __restrict__ Y,
                                                      float* __restrict__ out) {
    int idx = blockIdx.x * blockDim.x + threadIdx.x;   // over N*16 float4s
    if (idx >= N_NODES * 16) return;
    int n  = idx >> 4;
    int c4 = idx & 15;
    float4 v = *(const float4*)&Y[(size_t)n * WC_COLS + c4 * 4];
    v.x = 1.f / (1.f + __expf(-fmaxf(v.x, 0.f)));
    v.y = 1.f / (1.f + __expf(-fmaxf(v.y, 0.f)));
    v.z = 1.f / (1.f + __expf(-fmaxf(v.z, 0.f)));
    v.w = 1.f / (1.f + __expf(-fmaxf(v.w, 0.f)));
    *(float4*)&out[(size_t)n * 64 + c4 * 4] = v;
}

// ---------------------------------------------------------------------------
extern "C" void kernel_launch(void* const* d_in, const int* in_sizes, int n_in,
                              void* d_out, int out_size) {
    const float* node_emb = (const float*)d_in[0];      // [100000,128] f32
    const void*  src      = d_in[1];                    // [4,150000] int32 or int64
    const void*  dst      = d_in[2];                    // [4,150000]
    const float* W1       = (const float*)d_in[3];      // [4,128,64]
    const float* Wself1   = (const float*)d_in[4];      // [128,64]
    const float* W2       = (const float*)d_in[5];      // [4,64,64]
    const float* Wself2   = (const float*)d_in[6];      // [64,64]
    float*       out      = (float*)d_out;              // [100000,64]

    float *Y1, *Y2, *Wc1, *Wc2;
    cudaGetSymbolAddress((void**)&Y1, g_Y1);
    cudaGetSymbolAddress((void**)&Y2, g_Y2);
    cudaGetSymbolAddress((void**)&Wc1, g_Wc1);
    cudaGetSymbolAddress((void**)&Wc2, g_Wc2);

    // Detect index dtype (writes g_idx_is64)
    sniff_kernel<<<1, 256>>>((const unsigned int*)src);

    // Weight prep (tiny)
    prep_w_kernel<<<(128 * WC_COLS + 255) / 256, 256>>>(W1, Wself1, Wc1, 128);
    prep_w_kernel<<<(64 * WC_COLS + 255) / 256, 256>>>(W2, Wself2, Wc2, 64);

    const int mblocks = (N_NODES + 127) / 128;   // 782
    const int sblocks = (E_TOTAL * 16 + 255) / 256;

    // Layer 1: Y1 = node_emb @ Wc1; scatter messages into Y1[:,0:64]
    gemm_kernel<128, false><<<dim3(mblocks, 5), 256>>>(node_emb, 128, Wc1, Y1);
    scatter_kernel<<<sblocks, 256>>>(src, dst, Y1);

    // Layer 2: Y2 = relu(Y1[:,0:64]) @ Wc2; scatter into Y2[:,0:64]
    gemm_kernel<64, true><<<dim3(mblocks, 5), 256>>>(Y1, WC_COLS, Wc2, Y2);
    scatter_kernel<<<sblocks, 256>>>(src, dst, Y2);

    // out = sigmoid(relu(Y2[:,0:64]))
    sigmoid_kernel<<<(N_NODES * 16 + 255) / 256, 256>>>(Y2, out);
}